// round 15
// baseline (speedup 1.0000x reference)
#include <cuda_runtime.h>
#include <cuda_fp16.h>
#include <math.h>

#define Nn 50000
#define Ee 800000
#define Hh 128
#define Gg 512
#define NG 50
#define NI 6
#define TT 2048
#define TT2 32768

#define TAB_DMAX 8.6605f
#define DTf      (TAB_DMAX / (float)(TT - 1))
#define INV_DT2  ((float)(TT2 - 1) / TAB_DMAX)
#define GDELTA   (10.0f / 49.0f)
#define PI_OC    0.3141592653589793f

typedef unsigned long long ull;

// ---------------- scratch (static device globals; no allocs allowed) -------
__device__ __align__(16) float  g_h   [Nn * Hh];
__device__ __align__(16) __half g_hh  [Nn * Hh];   // fp16 shadow of h
__device__ __align__(16) __half g_xh  [Nn * Hh];
__device__ __align__(16) __half g_aggh[Nn * Hh];
__device__ __align__(16) float  g_tab [(size_t)NI * TT  * Hh];
__device__ __align__(16) __half g_tabh[(size_t)NI * TT2 * Hh];

// fp16 transposed weights [n][k]
__device__ __align__(16) __half g_w1t[NI * Hh * Hh];
__device__ __align__(16) __half g_w2t[NI * Hh * Hh];
__device__ __align__(16) __half g_w3t[NI * Hh * Hh];
__device__ __align__(16) __half g_owt[64 * Hh];

// CSR scratch
#define NBLK 196
__device__ int  g_deg [Nn];
__device__ int  g_off [Nn + 1];
__device__ int  g_part[NBLK];
__device__ ull  g_meta[Ee];   // low32 = col, high32 = fine table index

__device__ __forceinline__ float sspf(float v) {
    float sp = (v > 15.0f) ? v : log1pf(expf(v));
    return sp - 0.6931471805599453f;
}

// ---- packed f32x2 helpers ---------------------------------------------------
__device__ __forceinline__ ull f2fma(ull a, ull b, ull c) {
    ull d; asm("fma.rn.f32x2 %0, %1, %2, %3;" : "=l"(d) : "l"(a), "l"(b), "l"(c)); return d;
}
__device__ __forceinline__ ull f2add(ull a, ull b) {
    ull d; asm("add.rn.f32x2 %0, %1, %2;" : "=l"(d) : "l"(a), "l"(b)); return d;
}
__device__ __forceinline__ ull f2pack(float2 v) {
    ull d; asm("mov.b64 %0, {%1, %2};" : "=l"(d) : "f"(v.x), "f"(v.y)); return d;
}
__device__ __forceinline__ float2 f2unpack(ull v) {
    float2 r; asm("mov.b64 {%0, %1}, %2;" : "=f"(r.x), "=f"(r.y) : "l"(v)); return r;
}

// ---- mma helpers --------------------------------------------------------------
__device__ __forceinline__ unsigned sptr(const void* p) {
    return (unsigned)__cvta_generic_to_shared(p);
}
__device__ __forceinline__ void ldsm4(unsigned& r0, unsigned& r1, unsigned& r2, unsigned& r3,
                                      unsigned addr) {
    asm volatile("ldmatrix.sync.aligned.m8n8.x4.shared.b16 {%0,%1,%2,%3}, [%4];"
                 : "=r"(r0), "=r"(r1), "=r"(r2), "=r"(r3) : "r"(addr));
}
__device__ __forceinline__ void mma16816(float* c, const unsigned* a, const unsigned* b) {
    asm volatile("mma.sync.aligned.m16n8k16.row.col.f32.f16.f16.f32 "
                 "{%0,%1,%2,%3}, {%4,%5,%6,%7}, {%8,%9}, {%0,%1,%2,%3};"
                 : "+f"(c[0]), "+f"(c[1]), "+f"(c[2]), "+f"(c[3])
                 : "r"(a[0]), "r"(a[1]), "r"(a[2]), "r"(a[3]), "r"(b[0]), "r"(b[1]));
}

// ---------------- combined prelude 1: table + deg + emb/weights -------------
#define PRE1_TABLE 192
#define PRE1_DEG   3125
__global__ void k_pre1(const float* __restrict__ w1, const float* __restrict__ b1,
                       const float* __restrict__ w2, const float* __restrict__ b2,
                       const int* __restrict__ rowi,
                       const float* __restrict__ emb, const int* __restrict__ z,
                       const float* __restrict__ lin1w, const float* __restrict__ lin2w,
                       const float* __restrict__ linw, const float* __restrict__ ow1) {
    int tid = threadIdx.x;
    if (blockIdx.x < PRE1_TABLE) {
        extern __shared__ float sm[];
        float* ts  = sm;                  // 8*8*128
        float* rs  = ts + 8 * 8 * 128;    // 8*8*NG
        float* b1s = rs + 8 * 8 * NG;     // 128
        float* b2s = b1s + 128;           // 128

        int tb = blockIdx.x;
        int it = tb >> 5;
        int bx = tb & 31;
        const float* W1 = w1 + (size_t)it * NG * 128;
        const float* W2 = w2 + (size_t)it * 128 * 128;
        if (tid < 128) {
            b1s[tid] = b1[it * 128 + tid];
            b2s[tid] = b2[it * 128 + tid];
        }
        __syncthreads();

        int warp = tid >> 5, lane = tid & 31;
        float* tw = ts + warp * 8 * 128;
        float* rw = rs + warp * 8 * NG;
        const float GCO = -0.5f / (GDELTA * GDELTA);
        int base = (bx * 8 + warp) * 8;

        for (int j = lane; j < 8 * NG; j += 32) {
            int e = j / NG, k = j - e * NG;
            float d = (float)(base + e) * DTf;
            float u = d - (float)k * GDELTA;
            rw[j] = expf(GCO * u * u);
        }
        __syncwarp();

        float4 acc[8];
        float4 bb = *(const float4*)&b1s[4 * lane];
        #pragma unroll
        for (int e = 0; e < 8; e++) acc[e] = bb;
        #pragma unroll 5
        for (int k = 0; k < NG; k++) {
            float4 w = __ldg((const float4*)&W1[k * 128 + 4 * lane]);
            #pragma unroll
            for (int e = 0; e < 8; e++) {
                float r = rw[e * NG + k];
                acc[e].x = fmaf(r, w.x, acc[e].x);
                acc[e].y = fmaf(r, w.y, acc[e].y);
                acc[e].z = fmaf(r, w.z, acc[e].z);
                acc[e].w = fmaf(r, w.w, acc[e].w);
            }
        }
        #pragma unroll
        for (int e = 0; e < 8; e++) {
            float4 v;
            v.x = sspf(acc[e].x); v.y = sspf(acc[e].y);
            v.z = sspf(acc[e].z); v.w = sspf(acc[e].w);
            *(float4*)&tw[e * 128 + 4 * lane] = v;
        }
        __syncwarp();

        float4 bb2 = *(const float4*)&b2s[4 * lane];
        #pragma unroll
        for (int e = 0; e < 8; e++) acc[e] = bb2;
        #pragma unroll 4
        for (int k = 0; k < 128; k++) {
            float4 w = __ldg((const float4*)&W2[k * 128 + 4 * lane]);
            #pragma unroll
            for (int e = 0; e < 8; e++) {
                float t = tw[e * 128 + k];
                acc[e].x = fmaf(t, w.x, acc[e].x);
                acc[e].y = fmaf(t, w.y, acc[e].y);
                acc[e].z = fmaf(t, w.z, acc[e].z);
                acc[e].w = fmaf(t, w.w, acc[e].w);
            }
        }
        #pragma unroll
        for (int e = 0; e < 8; e++) {
            float d = (float)(base + e) * DTf;
            float Cc = 0.5f * (cosf(d * PI_OC) + 1.0f);
            float4 v = acc[e];
            v.x *= Cc; v.y *= Cc; v.z *= Cc; v.w *= Cc;
            *(float4*)&g_tab[((size_t)it * TT + (base + e)) * 128 + 4 * lane] = v;
        }
        return;
    }
    if (blockIdx.x < PRE1_TABLE + PRE1_DEG) {
        int e = (blockIdx.x - PRE1_TABLE) * 256 + tid;
        if (e < Ee) atomicAdd(&g_deg[rowi[e]], 1);
        return;
    }
    const int PER = NI * Hh * Hh;
    int i = (blockIdx.x - PRE1_TABLE - PRE1_DEG) * 256 + tid;
    if (i < Nn * 32) {
        int n = i >> 5, c = i & 31;
        float4 v = ((const float4*)emb)[(size_t)z[n] * 32 + c];
        ((float4*)g_h)[i] = v;
        __half2 h0 = __floats2half2_rn(v.x, v.y);
        __half2 h1 = __floats2half2_rn(v.z, v.w);
        uint2 pk;
        pk.x = *(unsigned*)&h0;
        pk.y = *(unsigned*)&h1;
        ((uint2*)g_hh)[i] = pk;
        return;
    }
    int idx = i - Nn * 32;
    if (idx < PER) {
        int it = idx / (Hh * Hh), r = idx % (Hh * Hh);
        int n = r / Hh, k = r % Hh;
        g_w1t[idx] = __float2half(lin1w[it * Hh * Hh + k * Hh + n]);
    } else if (idx < 2 * PER) {
        int j = idx - PER;
        int it = j / (Hh * Hh), r = j % (Hh * Hh);
        int n = r / Hh, k = r % Hh;
        g_w2t[j] = __float2half(lin2w[it * Hh * Hh + k * Hh + n]);
    } else if (idx < 3 * PER) {
        int j = idx - 2 * PER;
        int it = j / (Hh * Hh), r = j % (Hh * Hh);
        int n = r / Hh, k = r % Hh;
        g_w3t[j] = __float2half(linw[it * Hh * Hh + k * Hh + n]);
    } else if (idx < 3 * PER + 64 * Hh) {
        int j = idx - 3 * PER;
        int n = j / Hh, k = j % Hh;
        g_owt[j] = __float2half(ow1[k * 64 + n]);
    }
}

// ---------------- CSR: per-block partial sums --------------------------------
__global__ void k_part() {
    __shared__ int sm[256];
    int idx = blockIdx.x * 256 + threadIdx.x;
    sm[threadIdx.x] = (idx < Nn) ? g_deg[idx] : 0;
    __syncthreads();
    for (int o = 128; o; o >>= 1) {
        if (threadIdx.x < o) sm[threadIdx.x] += sm[threadIdx.x + o];
        __syncthreads();
    }
    if (threadIdx.x == 0) g_part[blockIdx.x] = sm[0];
}

// merged: scan partials locally + per-node offsets (off = END of node's range)
__global__ void k_fill2() {
    __shared__ int pp[256];
    __shared__ int sm[256];
    int t = threadIdx.x;
    int pv = (t < NBLK) ? g_part[t] : 0;
    pp[t] = pv;
    __syncthreads();
    for (int o = 1; o < 256; o <<= 1) {
        int u = (t >= o) ? pp[t - o] : 0;
        __syncthreads();
        pp[t] += u;
        __syncthreads();
    }
    int poff = (blockIdx.x == 0) ? 0 : pp[blockIdx.x - 1];
    if (blockIdx.x == 0 && t == 0) g_off[Nn] = Ee;

    int idx = blockIdx.x * 256 + t;
    int v = (idx < Nn) ? g_deg[idx] : 0;
    sm[t] = v;
    __syncthreads();
    for (int o = 1; o < 256; o <<= 1) {
        int u = (t >= o) ? sm[t - o] : 0;
        __syncthreads();
        sm[t] += u;
        __syncthreads();
    }
    if (idx < Nn) g_off[idx] = poff + sm[t] - v;
}

// ---------------- combined prelude 2: edge scatter + fine-table expand ------
// scatter uses count-down on g_deg (destroys g_deg; not needed afterwards)
#define PRE2_SCAT 3125
__global__ void k_pre2(const float* __restrict__ pos,
                       const int* __restrict__ rowi, const int* __restrict__ coli) {
    int tid = threadIdx.x;
    if (blockIdx.x < PRE2_SCAT) {
        int e = blockIdx.x * 256 + tid;
        if (e >= Ee) return;
        int r = rowi[e], c = coli[e];
        float dx = pos[3 * r + 0] - pos[3 * c + 0];
        float dy = pos[3 * r + 1] - pos[3 * c + 1];
        float dz = pos[3 * r + 2] - pos[3 * c + 2];
        float d = sqrtf(fmaf(dx, dx, fmaf(dy, dy, fmaf(dz, dz, 1e-12f))));
        int i0 = (int)(d * INV_DT2 + 0.5f);
        if (i0 > TT2 - 1) i0 = TT2 - 1;
        int s = g_off[r] + atomicSub(&g_deg[r], 1) - 1;
        g_meta[s] = (ull)(unsigned)c | ((ull)(unsigned)i0 << 32);
        return;
    }
    long long i = (long long)(blockIdx.x - PRE2_SCAT) * 256 + tid;
    if (i >= (long long)NI * TT2 * 32) return;
    int lane = (int)(i & 31);
    long long n = i >> 5;
    int t2 = (int)(n & (TT2 - 1));
    int it = (int)(n >> 15);
    float tp = (float)t2 * ((float)(TT - 1) / (float)(TT2 - 1));
    int i0 = (int)tp;
    if (i0 > TT - 2) i0 = TT - 2;
    float fr = tp - (float)i0;
    const float4* src = (const float4*)(g_tab + ((size_t)it * TT + i0) * Hh);
    float4 a = src[lane], b = src[32 + lane];
    float4 v;
    v.x = fmaf(fr, b.x - a.x, a.x);
    v.y = fmaf(fr, b.y - a.y, a.y);
    v.z = fmaf(fr, b.z - a.z, a.z);
    v.w = fmaf(fr, b.w - a.w, a.w);
    __half2 h0 = __floats2half2_rn(v.x, v.y);
    __half2 h1 = __floats2half2_rn(v.z, v.w);
    uint2 pk;
    pk.x = *(unsigned*)&h0;
    pk.y = *(unsigned*)&h1;
    ((uint2*)g_tabh)[n * 32 + lane] = pk;
}

// ---------------- lin1: fp16 in (raw copy), fp16 out -------------------------
// MT=64; WN=2, WM=4, MREP=1, NREP=8.
__global__ void k_mma1(const __half* __restrict__ in, const __half* __restrict__ Wt,
                       __half* __restrict__ outh, int M) {
    constexpr int NREP = 8, LDA = 136, MT = 64;
    extern __shared__ __half smh[];
    __half* As = smh;
    __half* Bs = smh + MT * LDA;

    int tid = threadIdx.x;
    for (int j = tid; j < 128 * 16; j += 256) {
        int n = j >> 4, c = j & 15;
        *(uint4*)&Bs[n * LDA + c * 8] = ((const uint4*)Wt)[j];
    }
    int lane = tid & 31, warp = tid >> 5;
    int wm = warp % 4, wn = warp / 4;
    int quad = lane >> 3, l8 = lane & 7;

    for (int mBase = blockIdx.x * MT; mBase < M; mBase += gridDim.x * MT) {
        __syncthreads();
        for (int j = tid; j < MT * 16; j += 256) {
            int r = j >> 4, c = j & 15;
            int gr = mBase + r;
            uint4 v = (gr < M) ? ((const uint4*)in)[(size_t)gr * 16 + c]
                               : make_uint4(0u, 0u, 0u, 0u);
            *(uint4*)&As[r * LDA + c * 8] = v;
        }
        __syncthreads();

        float acc[NREP][4];
        #pragma unroll
        for (int p = 0; p < NREP; p++)
            #pragma unroll
            for (int q = 0; q < 4; q++) acc[p][q] = 0.f;

        #pragma unroll
        for (int kk = 0; kk < 128; kk += 16) {
            unsigned a[4];
            {
                int row = wm * 16 + (quad & 1) * 8 + l8;
                ldsm4(a[0], a[1], a[2], a[3],
                      sptr(&As[row * LDA + kk + (quad >> 1) * 8]));
            }
            unsigned b[NREP][2];
            #pragma unroll
            for (int p = 0; p < NREP; p += 2) {
                int n = wn * 64 + p * 8 + (quad >> 1) * 8 + l8;
                unsigned r0, r1, r2, r3;
                ldsm4(r0, r1, r2, r3, sptr(&Bs[n * LDA + kk + (quad & 1) * 8]));
                b[p][0] = r0; b[p][1] = r1;
                b[p + 1][0] = r2; b[p + 1][1] = r3;
            }
            #pragma unroll
            for (int p = 0; p < NREP; p++)
                mma16816(acc[p], a, b[p]);
        }

        {
            int row0 = mBase + wm * 16 + (lane >> 2);
            #pragma unroll
            for (int p = 0; p < NREP; p++) {
                int coln = wn * 64 + p * 8 + (lane & 3) * 2;
                if (row0 < M) {
                    __half2 h = __floats2half2_rn(acc[p][0], acc[p][1]);
                    ((unsigned*)outh)[(size_t)row0 * 64 + coln / 2] = *(unsigned*)&h;
                }
                if (row0 + 8 < M) {
                    __half2 h = __floats2half2_rn(acc[p][2], acc[p][3]);
                    ((unsigned*)outh)[(size_t)(row0 + 8) * 64 + coln / 2] = *(unsigned*)&h;
                }
            }
        }
    }
}

// ---------------- fused lin2+lin: h += ssp(agg@W2+b2)@W3+b3; also h fp16 ----
__global__ void k_mma2(const __half* __restrict__ in, const __half* __restrict__ W2t,
                       const float* __restrict__ b2, const __half* __restrict__ W3t,
                       const float* __restrict__ b3, float* __restrict__ h,
                       __half* __restrict__ hh, int M) {
    constexpr int NREP = 8, LDA = 136, MT = 64;
    extern __shared__ __half smh[];
    __half* As  = smh;
    __half* B2s = smh + MT * LDA;
    __half* B3s = smh + (MT + 128) * LDA;

    int tid = threadIdx.x;
    for (int j = tid; j < 128 * 16; j += 256) {
        int n = j >> 4, c = j & 15;
        *(uint4*)&B2s[n * LDA + c * 8] = ((const uint4*)W2t)[j];
        *(uint4*)&B3s[n * LDA + c * 8] = ((const uint4*)W3t)[j];
    }
    int lane = tid & 31, warp = tid >> 5;
    int wm = warp % 4, wn = warp / 4;
    int quad = lane >> 3, l8 = lane & 7;

    float bv2[NREP][2], bv3[NREP][2];
    #pragma unroll
    for (int p = 0; p < NREP; p++) {
        int coln = wn * 64 + p * 8 + (lane & 3) * 2;
        bv2[p][0] = b2[coln]; bv2[p][1] = b2[coln + 1];
        bv3[p][0] = b3[coln]; bv3[p][1] = b3[coln + 1];
    }

    for (int mBase = blockIdx.x * MT; mBase < M; mBase += gridDim.x * MT) {
        __syncthreads();
        for (int j = tid; j < MT * 16; j += 256) {
            int r = j >> 4, c = j & 15;
            int gr = mBase + r;
            uint4 v = (gr < M) ? ((const uint4*)in)[(size_t)gr * 16 + c]
                               : make_uint4(0u, 0u, 0u, 0u);
            *(uint4*)&As[r * LDA + c * 8] = v;
        }
        __syncthreads();

        float acc[NREP][4];
        #pragma unroll
        for (int p = 0; p < NREP; p++)
            #pragma unroll
            for (int q = 0; q < 4; q++) acc[p][q] = 0.f;

        #pragma unroll
        for (int kk = 0; kk < 128; kk += 16) {
            unsigned a[4];
            {
                int row = wm * 16 + (quad & 1) * 8 + l8;
                ldsm4(a[0], a[1], a[2], a[3],
                      sptr(&As[row * LDA + kk + (quad >> 1) * 8]));
            }
            unsigned b[NREP][2];
            #pragma unroll
            for (int p = 0; p < NREP; p += 2) {
                int n = wn * 64 + p * 8 + (quad >> 1) * 8 + l8;
                unsigned r0, r1, r2, r3;
                ldsm4(r0, r1, r2, r3, sptr(&B2s[n * LDA + kk + (quad & 1) * 8]));
                b[p][0] = r0; b[p][1] = r1;
                b[p + 1][0] = r2; b[p + 1][1] = r3;
            }
            #pragma unroll
            for (int p = 0; p < NREP; p++)
                mma16816(acc[p], a, b[p]);
        }

        __syncthreads();
        {
            int r0 = wm * 16 + (lane >> 2);
            #pragma unroll
            for (int p = 0; p < NREP; p++) {
                int coln = wn * 64 + p * 8 + (lane & 3) * 2;
                float2 v0 = make_float2(acc[p][0] + bv2[p][0], acc[p][1] + bv2[p][1]);
                float2 v1 = make_float2(acc[p][2] + bv2[p][0], acc[p][3] + bv2[p][1]);
                v0.x = sspf(v0.x); v0.y = sspf(v0.y);
                v1.x = sspf(v1.x); v1.y = sspf(v1.y);
                *(__half2*)&As[r0 * LDA + coln] = __floats2half2_rn(v0.x, v0.y);
                *(__half2*)&As[(r0 + 8) * LDA + coln] = __floats2half2_rn(v1.x, v1.y);
            }
        }
        __syncthreads();

        #pragma unroll
        for (int p = 0; p < NREP; p++)
            #pragma unroll
            for (int q = 0; q < 4; q++) acc[p][q] = 0.f;

        #pragma unroll
        for (int kk = 0; kk < 128; kk += 16) {
            unsigned a[4];
            {
                int row = wm * 16 + (quad & 1) * 8 + l8;
                ldsm4(a[0], a[1], a[2], a[3],
                      sptr(&As[row * LDA + kk + (quad >> 1) * 8]));
            }
            unsigned b[NREP][2];
            #pragma unroll
            for (int p = 0; p < NREP; p += 2) {
                int n = wn * 64 + p * 8 + (quad >> 1) * 8 + l8;
                unsigned r0, r1, r2, r3;
                ldsm4(r0, r1, r2, r3, sptr(&B3s[n * LDA + kk + (quad & 1) * 8]));
                b[p][0] = r0; b[p][1] = r1;
                b[p + 1][0] = r2; b[p + 1][1] = r3;
            }
            #pragma unroll
            for (int p = 0; p < NREP; p++)
                mma16816(acc[p], a, b[p]);
        }

        {
            int row0 = mBase + wm * 16 + (lane >> 2);
            #pragma unroll
            for (int p = 0; p < NREP; p++) {
                int coln = wn * 64 + p * 8 + (lane & 3) * 2;
                if (row0 < M) {
                    float2* dst = (float2*)(h + (size_t)row0 * Hh + coln);
                    float2 o = *dst;
                    o.x += acc[p][0] + bv3[p][0];
                    o.y += acc[p][1] + bv3[p][1];
                    *dst = o;
                    __half2 hv = __floats2half2_rn(o.x, o.y);
                    ((unsigned*)hh)[(size_t)row0 * 64 + coln / 2] = *(unsigned*)&hv;
                }
                if (row0 + 8 < M) {
                    float2* dst = (float2*)(h + (size_t)(row0 + 8) * Hh + coln);
                    float2 o = *dst;
                    o.x += acc[p][2] + bv3[p][0];
                    o.y += acc[p][3] + bv3[p][1];
                    *dst = o;
                    __half2 hv = __floats2half2_rn(o.x, o.y);
                    ((unsigned*)hh)[(size_t)(row0 + 8) * 64 + coln / 2] = *(unsigned*)&hv;
                }
            }
        }
    }
}

// ---------------- readout GEMM with fused energy reduction -------------------
__global__ void k_mmaE(const float* __restrict__ in, const __half* __restrict__ Wt,
                       const float* __restrict__ bias, const float* __restrict__ ow2,
                       const float* __restrict__ ob2, const int* __restrict__ batch,
                       float* __restrict__ out, int M) {
    constexpr int NREP = 8, LDA = 136, MT = 128, NOUT = 64;
    extern __shared__ __half smh[];
    __half* As = smh;
    __half* Bs = smh + MT * LDA;

    int tid = threadIdx.x;
    for (int j = tid; j < NOUT * 16; j += 256) {
        int n = j >> 4, c = j & 15;
        *(uint4*)&Bs[n * LDA + c * 8] = ((const uint4*)Wt)[j];
    }
    int lane = tid & 31, warp = tid >> 5;
    int quad = lane >> 3, l8 = lane & 7;

    float bv[NREP][2], wv[NREP][2];
    #pragma unroll
    for (int p = 0; p < NREP; p++) {
        int coln = p * 8 + (lane & 3) * 2;
        bv[p][0] = bias[coln]; bv[p][1] = bias[coln + 1];
        wv[p][0] = ow2[coln];  wv[p][1] = ow2[coln + 1];
    }
    float ob = ob2[0];

    for (int mBase = blockIdx.x * MT; mBase < M; mBase += gridDim.x * MT) {
        __syncthreads();
        for (int j = tid; j < MT * 32; j += 256) {
            int r = j >> 5, c4 = j & 31;
            int gr = mBase + r;
            float4 v = (gr < M) ? ((const float4*)in)[(size_t)gr * 32 + c4]
                                : make_float4(0.f, 0.f, 0.f, 0.f);
            __half2 h0 = __floats2half2_rn(v.x, v.y);
            __half2 h1 = __floats2half2_rn(v.z, v.w);
            uint2 pk;
            pk.x = *(unsigned*)&h0;
            pk.y = *(unsigned*)&h1;
            *(uint2*)&As[r * LDA + c4 * 4] = pk;
        }
        __syncthreads();

        float acc[NREP][4];
        #pragma unroll
        for (int p = 0; p < NREP; p++)
            #pragma unroll
            for (int q = 0; q < 4; q++) acc[p][q] = 0.f;

        #pragma unroll
        for (int kk = 0; kk < 128; kk += 16) {
            unsigned a[4];
            {
                int row = warp * 16 + (quad & 1) * 8 + l8;
                ldsm4(a[0], a[1], a[2], a[3], sptr(&As[row * LDA + kk + (quad >> 1) * 8]));
            }
            unsigned b[NREP][2];
            #pragma unroll
            for (int p = 0; p < NREP; p += 2) {
                int n = p * 8 + (quad >> 1) * 8 + l8;
                unsigned r0, r1, r2, r3;
                ldsm4(r0, r1, r2, r3, sptr(&Bs[n * LDA + kk + (quad & 1) * 8]));
                b[p][0] = r0; b[p][1] = r1;
                b[p + 1][0] = r2; b[p + 1][1] = r3;
            }
            #pragma unroll
            for (int p = 0; p < NREP; p++)
                mma16816(acc[p], a, b[p]);
        }

        float e0 = 0.f, e1 = 0.f;
        #pragma unroll
        for (int p = 0; p < NREP; p++) {
            float2 v0 = make_float2(sspf(acc[p][0] + bv[p][0]), sspf(acc[p][1] + bv[p][1]));
            float2 v1 = make_float2(sspf(acc[p][2] + bv[p][0]), sspf(acc[p][3] + bv[p][1]));
            e0 = fmaf(v0.x, wv[p][0], fmaf(v0.y, wv[p][1], e0));
            e1 = fmaf(v1.x, wv[p][0], fmaf(v1.y, wv[p][1], e1));
        }
        e0 += __shfl_xor_sync(0xffffffffu, e0, 1);
        e0 += __shfl_xor_sync(0xffffffffu, e0, 2);
        e1 += __shfl_xor_sync(0xffffffffu, e1, 1);
        e1 += __shfl_xor_sync(0xffffffffu, e1, 2);
        if ((lane & 3) == 0) {
            int row0 = mBase + warp * 16 + (lane >> 2);
            if (row0 < M)     atomicAdd(&out[batch[row0]],     e0 + ob);
            if (row0 + 8 < M) atomicAdd(&out[batch[row0 + 8]], e1 + ob);
        }
    }
}

// ---------------- aggregation: one warp per node, unroll-4, fp16 out --------
__global__ void k_agg(int it) {
    const uint2* __restrict__ tab = (const uint2*)(g_tabh + (size_t)it * TT2 * Hh);
    const uint2* __restrict__ X   = (const uint2*)g_xh;
    int w = (blockIdx.x * blockDim.x + threadIdx.x) >> 5;
    if (w >= Nn) return;
    int lane = threadIdx.x & 31;
    int s   = g_off[w];
    int end = g_off[w + 1];
    ull a0 = 0ull, a1 = 0ull, b0 = 0ull, b1 = 0ull;
    ull c0 = 0ull, c1 = 0ull, d0 = 0ull, d1 = 0ull;
    for (; s + 4 <= end; s += 4) {
        ull m0 = __ldg(&g_meta[s]),     m1 = __ldg(&g_meta[s + 1]);
        ull m2 = __ldg(&g_meta[s + 2]), m3 = __ldg(&g_meta[s + 3]);
        uint2 t0 = tab[(size_t)(m0 >> 32) * 32 + lane];
        uint2 x0 = X  [(size_t)(unsigned)m0 * 32 + lane];
        uint2 t1 = tab[(size_t)(m1 >> 32) * 32 + lane];
        uint2 x1 = X  [(size_t)(unsigned)m1 * 32 + lane];
        uint2 t2 = tab[(size_t)(m2 >> 32) * 32 + lane];
        uint2 x2 = X  [(size_t)(unsigned)m2 * 32 + lane];
        uint2 t3 = tab[(size_t)(m3 >> 32) * 32 + lane];
        uint2 x3 = X  [(size_t)(unsigned)m3 * 32 + lane];
        a0 = f2fma(f2pack(__half22float2(*(__half2*)&x0.x)), f2pack(__half22float2(*(__half2*)&t0.x)), a0);
        a1 = f2fma(f2pack(__half22float2(*(__half2*)&x0.y)), f2pack(__half22float2(*(__half2*)&t0.y)), a1);
        b0 = f2fma(f2pack(__half22float2(*(__half2*)&x1.x)), f2pack(__half22float2(*(__half2*)&t1.x)), b0);
        b1 = f2fma(f2pack(__half22float2(*(__half2*)&x1.y)), f2pack(__half22float2(*(__half2*)&t1.y)), b1);
        c0 = f2fma(f2pack(__half22float2(*(__half2*)&x2.x)), f2pack(__half22float2(*(__half2*)&t2.x)), c0);
        c1 = f2fma(f2pack(__half22float2(*(__half2*)&x2.y)), f2pack(__half22float2(*(__half2*)&t2.y)), c1);
        d0 = f2fma(f2pack(__half22float2(*(__half2*)&x3.x)), f2pack(__half22float2(*(__half2*)&t3.x)), d0);
        d1 = f2fma(f2pack(__half22float2(*(__half2*)&x3.y)), f2pack(__half22float2(*(__half2*)&t3.y)), d1);
    }
    for (; s < end; s++) {
        ull m0 = __ldg(&g_meta[s]);
        uint2 t0 = tab[(size_t)(m0 >> 32) * 32 + lane];
        uint2 x0 = X  [(size_t)(unsigned)m0 * 32 + lane];
        a0 = f2fma(f2pack(__half22float2(*(__half2*)&x0.x)), f2pack(__half22float2(*(__half2*)&t0.x)), a0);
        a1 = f2fma(f2pack(__half22float2(*(__half2*)&x0.y)), f2pack(__half22float2(*(__half2*)&t0.y)), a1);
    }
    a0 = f2add(f2add(a0, b0), f2add(c0, d0));
    a1 = f2add(f2add(a1, b1), f2add(c1, d1));
    float2 p0 = f2unpack(a0);
    float2 p1 = f2unpack(a1);
    __half2 h0 = __floats2half2_rn(p0.x, p0.y);
    __half2 h1 = __floats2half2_rn(p1.x, p1.y);
    uint2 pk;
    pk.x = *(unsigned*)&h0;
    pk.y = *(unsigned*)&h1;
    ((uint2*)g_aggh)[(size_t)w * 32 + lane] = pk;
}

// ---------------------------------------------------------------------------
extern "C" void kernel_launch(void* const* d_in, const int* in_sizes, int n_in,
                              void* d_out, int out_size) {
    const float* pos   = (const float*)d_in[0];
    const float* emb   = (const float*)d_in[1];
    const float* w1    = (const float*)d_in[2];
    const float* b1    = (const float*)d_in[3];
    const float* w2    = (const float*)d_in[4];
    const float* b2    = (const float*)d_in[5];
    const float* lin1w = (const float*)d_in[6];
    const float* lin2w = (const float*)d_in[7];
    const float* lin2b = (const float*)d_in[8];
    const float* linw  = (const float*)d_in[9];
    const float* linb  = (const float*)d_in[10];
    const float* ow1   = (const float*)d_in[11];
    const float* ob1   = (const float*)d_in[12];
    const float* ow2   = (const float*)d_in[13];
    const float* ob2   = (const float*)d_in[14];
    const int*   z     = (const int*)d_in[15];
    const int*   batch = (const int*)d_in[16];
    const int*   row   = (const int*)d_in[17];
    const int*   col   = row + Ee;
    float* out = (float*)d_out;

    const size_t smem_pre1 = (size_t)(8 * 8 * 128 + 8 * 8 * NG + 256) * 4;
    const size_t smem_lin1 = (size_t)(64 + 128) * 136 * 2;
    const size_t smem_mmaE = (size_t)(128 + 64) * 136 * 2;
    const size_t smem_mma2 = (size_t)(64 + 256) * 136 * 2;
    cudaFuncSetAttribute(k_pre1, cudaFuncAttributeMaxDynamicSharedMemorySize, (int)smem_pre1);
    cudaFuncSetAttribute(k_mma1, cudaFuncAttributeMaxDynamicSharedMemorySize, (int)smem_lin1);
    cudaFuncSetAttribute(k_mmaE, cudaFuncAttributeMaxDynamicSharedMemorySize, (int)smem_mmaE);
    cudaFuncSetAttribute(k_mma2, cudaFuncAttributeMaxDynamicSharedMemorySize, (int)smem_mma2);

    float *ph;
    __half *phh, *pxh, *paggh, *pw1t, *pw2t, *pw3t, *powt;
    cudaGetSymbolAddress((void**)&ph,    g_h);
    cudaGetSymbolAddress((void**)&phh,   g_hh);
    cudaGetSymbolAddress((void**)&pxh,   g_xh);
    cudaGetSymbolAddress((void**)&paggh, g_aggh);
    cudaGetSymbolAddress((void**)&pw1t,  g_w1t);
    cudaGetSymbolAddress((void**)&pw2t,  g_w2t);
    cudaGetSymbolAddress((void**)&pw3t,  g_w3t);
    cudaGetSymbolAddress((void**)&powt,  g_owt);
    int *pdeg;
    cudaGetSymbolAddress((void**)&pdeg, g_deg);

    cudaMemsetAsync(out, 0, Gg * sizeof(float), 0);
    cudaMemsetAsync(pdeg, 0, Nn * sizeof(int), 0);

    const int EMBWT_N = Nn * 32 + 3 * NI * Hh * Hh + 64 * Hh;
    const int PRE1_B  = PRE1_TABLE + PRE1_DEG + (EMBWT_N + 255) / 256;
    const int PRE2_B  = PRE2_SCAT + (int)(((long long)NI * TT2 * 32 + 255) / 256);

    k_pre1<<<PRE1_B, 256, smem_pre1>>>(w1, b1, w2, b2, row, emb, z, lin1w, lin2w, linw, ow1);
    k_part <<<NBLK, 256>>>();
    k_fill2<<<NBLK, 256>>>();
    k_pre2<<<PRE2_B, 256>>>(pos, row, col);

    for (int i = 0; i < NI; i++) {
        k_mma1<<<592, 256, smem_lin1>>>(phh, pw1t + (size_t)i * Hh * Hh, pxh, Nn);
        k_agg<<<(Nn * 32 + 255) / 256, 256>>>(i);
        k_mma2<<<592, 256, smem_mma2>>>(paggh, pw2t + (size_t)i * Hh * Hh, lin2b + i * 128,
                                        pw3t + (size_t)i * Hh * Hh, linb + i * 128, ph, phh, Nn);
    }

    k_mmaE<<<391, 256, smem_mmaE>>>(ph, powt, ob1, ow2, ob2, batch, out, Nn);
}

// round 16
// speedup vs baseline: 1.0465x; 1.0465x over previous
#include <cuda_runtime.h>
#include <cuda_fp16.h>
#include <math.h>

#define Nn 50000
#define Ee 800000
#define Hh 128
#define Gg 512
#define NG 50
#define NI 6
#define TT 2048
#define TT2 32768

#define TAB_DMAX 8.6605f
#define DTf      (TAB_DMAX / (float)(TT - 1))
#define INV_DT2  ((float)(TT2 - 1) / TAB_DMAX)
#define GDELTA   (10.0f / 49.0f)
#define PI_OC    0.3141592653589793f

typedef unsigned long long ull;

// ---------------- scratch (static device globals; no allocs allowed) -------
__device__ __align__(16) float  g_h   [Nn * Hh];
__device__ __align__(16) __half g_xh  [Nn * Hh];
__device__ __align__(16) __half g_aggh[Nn * Hh];
__device__ __align__(16) float  g_tab [(size_t)NI * TT  * Hh];
__device__ __align__(16) __half g_tabh[(size_t)NI * TT2 * Hh];

// fp16 transposed weights [n][k]
__device__ __align__(16) __half g_w1t[NI * Hh * Hh];
__device__ __align__(16) __half g_w2t[NI * Hh * Hh];
__device__ __align__(16) __half g_w3t[NI * Hh * Hh];
__device__ __align__(16) __half g_owt[64 * Hh];

// CSR scratch
#define NBLK 196
__device__ int  g_deg [Nn];
__device__ int  g_off [Nn + 1];
__device__ int  g_part[NBLK];
__device__ ull  g_meta[Ee];   // low32 = col, high32 = fine table index

__device__ __forceinline__ float sspf(float v) {
    float sp = (v > 15.0f) ? v : log1pf(expf(v));
    return sp - 0.6931471805599453f;
}

// ---- packed f32x2 helpers ---------------------------------------------------
__device__ __forceinline__ ull f2fma(ull a, ull b, ull c) {
    ull d; asm("fma.rn.f32x2 %0, %1, %2, %3;" : "=l"(d) : "l"(a), "l"(b), "l"(c)); return d;
}
__device__ __forceinline__ ull f2add(ull a, ull b) {
    ull d; asm("add.rn.f32x2 %0, %1, %2;" : "=l"(d) : "l"(a), "l"(b)); return d;
}
__device__ __forceinline__ ull f2pack(float2 v) {
    ull d; asm("mov.b64 %0, {%1, %2};" : "=l"(d) : "f"(v.x), "f"(v.y)); return d;
}
__device__ __forceinline__ float2 f2unpack(ull v) {
    float2 r; asm("mov.b64 {%0, %1}, %2;" : "=f"(r.x), "=f"(r.y) : "l"(v)); return r;
}

// ---- mma helpers --------------------------------------------------------------
__device__ __forceinline__ unsigned sptr(const void* p) {
    return (unsigned)__cvta_generic_to_shared(p);
}
__device__ __forceinline__ void ldsm4(unsigned& r0, unsigned& r1, unsigned& r2, unsigned& r3,
                                      unsigned addr) {
    asm volatile("ldmatrix.sync.aligned.m8n8.x4.shared.b16 {%0,%1,%2,%3}, [%4];"
                 : "=r"(r0), "=r"(r1), "=r"(r2), "=r"(r3) : "r"(addr));
}
__device__ __forceinline__ void mma16816(float* c, const unsigned* a, const unsigned* b) {
    asm volatile("mma.sync.aligned.m16n8k16.row.col.f32.f16.f16.f32 "
                 "{%0,%1,%2,%3}, {%4,%5,%6,%7}, {%8,%9}, {%0,%1,%2,%3};"
                 : "+f"(c[0]), "+f"(c[1]), "+f"(c[2]), "+f"(c[3])
                 : "r"(a[0]), "r"(a[1]), "r"(a[2]), "r"(a[3]), "r"(b[0]), "r"(b[1]));
}

// ---------------- combined prelude 1: table + deg + emb/weights -------------
#define PRE1_TABLE 192
#define PRE1_DEG   3125
__global__ void k_pre1(const float* __restrict__ w1, const float* __restrict__ b1,
                       const float* __restrict__ w2, const float* __restrict__ b2,
                       const int* __restrict__ rowi,
                       const float* __restrict__ emb, const int* __restrict__ z,
                       const float* __restrict__ lin1w, const float* __restrict__ lin2w,
                       const float* __restrict__ linw, const float* __restrict__ ow1) {
    int tid = threadIdx.x;
    if (blockIdx.x < PRE1_TABLE) {
        extern __shared__ float sm[];
        float* ts  = sm;                  // 8*8*128
        float* rs  = ts + 8 * 8 * 128;    // 8*8*NG
        float* b1s = rs + 8 * 8 * NG;     // 128
        float* b2s = b1s + 128;           // 128

        int tb = blockIdx.x;
        int it = tb >> 5;
        int bx = tb & 31;
        const float* W1 = w1 + (size_t)it * NG * 128;
        const float* W2 = w2 + (size_t)it * 128 * 128;
        if (tid < 128) {
            b1s[tid] = b1[it * 128 + tid];
            b2s[tid] = b2[it * 128 + tid];
        }
        __syncthreads();

        int warp = tid >> 5, lane = tid & 31;
        float* tw = ts + warp * 8 * 128;
        float* rw = rs + warp * 8 * NG;
        const float GCO = -0.5f / (GDELTA * GDELTA);
        int base = (bx * 8 + warp) * 8;

        for (int j = lane; j < 8 * NG; j += 32) {
            int e = j / NG, k = j - e * NG;
            float d = (float)(base + e) * DTf;
            float u = d - (float)k * GDELTA;
            rw[j] = expf(GCO * u * u);
        }
        __syncwarp();

        float4 acc[8];
        float4 bb = *(const float4*)&b1s[4 * lane];
        #pragma unroll
        for (int e = 0; e < 8; e++) acc[e] = bb;
        #pragma unroll 5
        for (int k = 0; k < NG; k++) {
            float4 w = __ldg((const float4*)&W1[k * 128 + 4 * lane]);
            #pragma unroll
            for (int e = 0; e < 8; e++) {
                float r = rw[e * NG + k];
                acc[e].x = fmaf(r, w.x, acc[e].x);
                acc[e].y = fmaf(r, w.y, acc[e].y);
                acc[e].z = fmaf(r, w.z, acc[e].z);
                acc[e].w = fmaf(r, w.w, acc[e].w);
            }
        }
        #pragma unroll
        for (int e = 0; e < 8; e++) {
            float4 v;
            v.x = sspf(acc[e].x); v.y = sspf(acc[e].y);
            v.z = sspf(acc[e].z); v.w = sspf(acc[e].w);
            *(float4*)&tw[e * 128 + 4 * lane] = v;
        }
        __syncwarp();

        float4 bb2 = *(const float4*)&b2s[4 * lane];
        #pragma unroll
        for (int e = 0; e < 8; e++) acc[e] = bb2;
        #pragma unroll 4
        for (int k = 0; k < 128; k++) {
            float4 w = __ldg((const float4*)&W2[k * 128 + 4 * lane]);
            #pragma unroll
            for (int e = 0; e < 8; e++) {
                float t = tw[e * 128 + k];
                acc[e].x = fmaf(t, w.x, acc[e].x);
                acc[e].y = fmaf(t, w.y, acc[e].y);
                acc[e].z = fmaf(t, w.z, acc[e].z);
                acc[e].w = fmaf(t, w.w, acc[e].w);
            }
        }
        #pragma unroll
        for (int e = 0; e < 8; e++) {
            float d = (float)(base + e) * DTf;
            float Cc = 0.5f * (cosf(d * PI_OC) + 1.0f);
            float4 v = acc[e];
            v.x *= Cc; v.y *= Cc; v.z *= Cc; v.w *= Cc;
            *(float4*)&g_tab[((size_t)it * TT + (base + e)) * 128 + 4 * lane] = v;
        }
        return;
    }
    if (blockIdx.x < PRE1_TABLE + PRE1_DEG) {
        int e = (blockIdx.x - PRE1_TABLE) * 256 + tid;
        if (e < Ee) atomicAdd(&g_deg[rowi[e]], 1);
        return;
    }
    const int PER = NI * Hh * Hh;
    int i = (blockIdx.x - PRE1_TABLE - PRE1_DEG) * 256 + tid;
    if (i < Nn * 32) {
        int n = i >> 5, c = i & 31;
        ((float4*)g_h)[i] = ((const float4*)emb)[(size_t)z[n] * 32 + c];
        return;
    }
    int idx = i - Nn * 32;
    if (idx < PER) {
        int it = idx / (Hh * Hh), r = idx % (Hh * Hh);
        int n = r / Hh, k = r % Hh;
        g_w1t[idx] = __float2half(lin1w[it * Hh * Hh + k * Hh + n]);
    } else if (idx < 2 * PER) {
        int j = idx - PER;
        int it = j / (Hh * Hh), r = j % (Hh * Hh);
        int n = r / Hh, k = r % Hh;
        g_w2t[j] = __float2half(lin2w[it * Hh * Hh + k * Hh + n]);
    } else if (idx < 3 * PER) {
        int j = idx - 2 * PER;
        int it = j / (Hh * Hh), r = j % (Hh * Hh);
        int n = r / Hh, k = r % Hh;
        g_w3t[j] = __float2half(linw[it * Hh * Hh + k * Hh + n]);
    } else if (idx < 3 * PER + 64 * Hh) {
        int j = idx - 3 * PER;
        int n = j / Hh, k = j % Hh;
        g_owt[j] = __float2half(ow1[k * 64 + n]);
    }
}

// ---------------- CSR: per-block partial sums --------------------------------
__global__ void k_part() {
    __shared__ int sm[256];
    int idx = blockIdx.x * 256 + threadIdx.x;
    sm[threadIdx.x] = (idx < Nn) ? g_deg[idx] : 0;
    __syncthreads();
    for (int o = 128; o; o >>= 1) {
        if (threadIdx.x < o) sm[threadIdx.x] += sm[threadIdx.x + o];
        __syncthreads();
    }
    if (threadIdx.x == 0) g_part[blockIdx.x] = sm[0];
}

// merged: scan partials locally + per-node offsets
__global__ void k_fill2() {
    __shared__ int pp[256];
    __shared__ int sm[256];
    int t = threadIdx.x;
    int pv = (t < NBLK) ? g_part[t] : 0;
    pp[t] = pv;
    __syncthreads();
    for (int o = 1; o < 256; o <<= 1) {
        int u = (t >= o) ? pp[t - o] : 0;
        __syncthreads();
        pp[t] += u;
        __syncthreads();
    }
    int poff = (blockIdx.x == 0) ? 0 : pp[blockIdx.x - 1];
    if (blockIdx.x == 0 && t == 0) g_off[Nn] = Ee;

    int idx = blockIdx.x * 256 + t;
    int v = (idx < Nn) ? g_deg[idx] : 0;
    sm[t] = v;
    __syncthreads();
    for (int o = 1; o < 256; o <<= 1) {
        int u = (t >= o) ? sm[t - o] : 0;
        __syncthreads();
        sm[t] += u;
        __syncthreads();
    }
    if (idx < Nn) g_off[idx] = poff + sm[t] - v;
}

// ---------------- combined prelude 2: edge scatter + fine-table expand ------
// scatter uses count-down on g_deg (destroys g_deg; not needed afterwards)
#define PRE2_SCAT 3125
__global__ void k_pre2(const float* __restrict__ pos,
                       const int* __restrict__ rowi, const int* __restrict__ coli) {
    int tid = threadIdx.x;
    if (blockIdx.x < PRE2_SCAT) {
        int e = blockIdx.x * 256 + tid;
        if (e >= Ee) return;
        int r = rowi[e], c = coli[e];
        float dx = pos[3 * r + 0] - pos[3 * c + 0];
        float dy = pos[3 * r + 1] - pos[3 * c + 1];
        float dz = pos[3 * r + 2] - pos[3 * c + 2];
        float d = sqrtf(fmaf(dx, dx, fmaf(dy, dy, fmaf(dz, dz, 1e-12f))));
        int i0 = (int)(d * INV_DT2 + 0.5f);
        if (i0 > TT2 - 1) i0 = TT2 - 1;
        int s = g_off[r] + atomicSub(&g_deg[r], 1) - 1;
        g_meta[s] = (ull)(unsigned)c | ((ull)(unsigned)i0 << 32);
        return;
    }
    long long i = (long long)(blockIdx.x - PRE2_SCAT) * 256 + tid;
    if (i >= (long long)NI * TT2 * 32) return;
    int lane = (int)(i & 31);
    long long n = i >> 5;
    int t2 = (int)(n & (TT2 - 1));
    int it = (int)(n >> 15);
    float tp = (float)t2 * ((float)(TT - 1) / (float)(TT2 - 1));
    int i0 = (int)tp;
    if (i0 > TT - 2) i0 = TT - 2;
    float fr = tp - (float)i0;
    const float4* src = (const float4*)(g_tab + ((size_t)it * TT + i0) * Hh);
    float4 a = src[lane], b = src[32 + lane];
    float4 v;
    v.x = fmaf(fr, b.x - a.x, a.x);
    v.y = fmaf(fr, b.y - a.y, a.y);
    v.z = fmaf(fr, b.z - a.z, a.z);
    v.w = fmaf(fr, b.w - a.w, a.w);
    __half2 h0 = __floats2half2_rn(v.x, v.y);
    __half2 h1 = __floats2half2_rn(v.z, v.w);
    uint2 pk;
    pk.x = *(unsigned*)&h0;
    pk.y = *(unsigned*)&h1;
    ((uint2*)g_tabh)[n * 32 + lane] = pk;
}

// ---------------- HMMA node GEMM (lin1: fp32 in, fp16 out) -------------------
template<int NOUT, int MT, bool BIAS, bool ACT, bool RES, bool OUTH>
__global__ void k_mma(const float* __restrict__ in, const __half* __restrict__ Wt,
                      const float* __restrict__ bias, void* __restrict__ outv, int M) {
    constexpr int WN   = (NOUT == 128) ? 2 : 1;
    constexpr int WM   = 8 / WN;
    constexpr int MREP = MT / (WM * 16);
    constexpr int NREP = NOUT / (WN * 8);
    constexpr int LDA  = 136;
    extern __shared__ __half smh[];
    __half* As = smh;
    __half* Bs = smh + MT * LDA;

    int tid = threadIdx.x;
    for (int j = tid; j < NOUT * 16; j += 256) {
        int n = j >> 4, c = j & 15;
        *(uint4*)&Bs[n * LDA + c * 8] = ((const uint4*)Wt)[j];
    }
    int lane = tid & 31, warp = tid >> 5;
    int wm = warp % WM, wn = warp / WM;
    int quad = lane >> 3, l8 = lane & 7;

    float bv[NREP][2];
    if (BIAS) {
        #pragma unroll
        for (int p = 0; p < NREP; p++) {
            int coln = wn * (NREP * 8) + p * 8 + (lane & 3) * 2;
            bv[p][0] = bias[coln];
            bv[p][1] = bias[coln + 1];
        }
    }

    for (int mBase = blockIdx.x * MT; mBase < M; mBase += gridDim.x * MT) {
        __syncthreads();
        for (int j = tid; j < MT * 32; j += 256) {
            int r = j >> 5, c4 = j & 31;
            int gr = mBase + r;
            float4 v = (gr < M) ? ((const float4*)in)[(size_t)gr * 32 + c4]
                                : make_float4(0.f, 0.f, 0.f, 0.f);
            __half2 h0 = __floats2half2_rn(v.x, v.y);
            __half2 h1 = __floats2half2_rn(v.z, v.w);
            uint2 pk;
            pk.x = *(unsigned*)&h0;
            pk.y = *(unsigned*)&h1;
            *(uint2*)&As[r * LDA + c4 * 4] = pk;
        }
        __syncthreads();

        float acc[MREP][NREP][4];
        #pragma unroll
        for (int mr = 0; mr < MREP; mr++)
            #pragma unroll
            for (int p = 0; p < NREP; p++)
                #pragma unroll
                for (int q = 0; q < 4; q++) acc[mr][p][q] = 0.f;

        #pragma unroll
        for (int kk = 0; kk < 128; kk += 16) {
            unsigned a[MREP][4];
            #pragma unroll
            for (int mr = 0; mr < MREP; mr++) {
                int row = wm * (MREP * 16) + mr * 16 + (quad & 1) * 8 + l8;
                int col = kk + (quad >> 1) * 8;
                ldsm4(a[mr][0], a[mr][1], a[mr][2], a[mr][3], sptr(&As[row * LDA + col]));
            }
            unsigned b[NREP][2];
            #pragma unroll
            for (int p = 0; p < NREP; p += 2) {
                int n = wn * (NREP * 8) + p * 8 + (quad >> 1) * 8 + l8;
                int col = kk + (quad & 1) * 8;
                unsigned r0, r1, r2, r3;
                ldsm4(r0, r1, r2, r3, sptr(&Bs[n * LDA + col]));
                b[p][0] = r0; b[p][1] = r1;
                b[p + 1][0] = r2; b[p + 1][1] = r3;
            }
            #pragma unroll
            for (int mr = 0; mr < MREP; mr++)
                #pragma unroll
                for (int p = 0; p < NREP; p++)
                    mma16816(acc[mr][p], a[mr], b[p]);
        }

        #pragma unroll
        for (int mr = 0; mr < MREP; mr++) {
            int row0 = mBase + wm * (MREP * 16) + mr * 16 + (lane >> 2);
            #pragma unroll
            for (int p = 0; p < NREP; p++) {
                int coln = wn * (NREP * 8) + p * 8 + (lane & 3) * 2;
                float2 v0 = make_float2(acc[mr][p][0], acc[mr][p][1]);
                float2 v1 = make_float2(acc[mr][p][2], acc[mr][p][3]);
                if (BIAS) {
                    v0.x += bv[p][0]; v0.y += bv[p][1];
                    v1.x += bv[p][0]; v1.y += bv[p][1];
                }
                if (ACT) {
                    v0.x = sspf(v0.x); v0.y = sspf(v0.y);
                    v1.x = sspf(v1.x); v1.y = sspf(v1.y);
                }
                if (row0 < M) {
                    if (OUTH) {
                        __half2 h = __floats2half2_rn(v0.x, v0.y);
                        ((unsigned*)outv)[(size_t)row0 * (NOUT / 2) + coln / 2] = *(unsigned*)&h;
                    } else {
                        float2* dst = (float2*)((float*)outv + (size_t)row0 * NOUT + coln);
                        if (RES) { float2 o = *dst; v0.x += o.x; v0.y += o.y; }
                        *dst = v0;
                    }
                }
                if (row0 + 8 < M) {
                    if (OUTH) {
                        __half2 h = __floats2half2_rn(v1.x, v1.y);
                        ((unsigned*)outv)[(size_t)(row0 + 8) * (NOUT / 2) + coln / 2] = *(unsigned*)&h;
                    } else {
                        float2* dst = (float2*)((float*)outv + (size_t)(row0 + 8) * NOUT + coln);
                        if (RES) { float2 o = *dst; v1.x += o.x; v1.y += o.y; }
                        *dst = v1;
                    }
                }
            }
        }
    }
}

// ---------------- fused lin2+lin: h += ssp(agg@W2+b2)@W3+b3 ------------------
__global__ void k_mma2(const __half* __restrict__ in, const __half* __restrict__ W2t,
                       const float* __restrict__ b2, const __half* __restrict__ W3t,
                       const float* __restrict__ b3, float* __restrict__ h, int M) {
    constexpr int NREP = 8, LDA = 136, MT = 64;
    extern __shared__ __half smh[];
    __half* As  = smh;
    __half* B2s = smh + MT * LDA;
    __half* B3s = smh + (MT + 128) * LDA;

    int tid = threadIdx.x;
    for (int j = tid; j < 128 * 16; j += 256) {
        int n = j >> 4, c = j & 15;
        *(uint4*)&B2s[n * LDA + c * 8] = ((const uint4*)W2t)[j];
        *(uint4*)&B3s[n * LDA + c * 8] = ((const uint4*)W3t)[j];
    }
    int lane = tid & 31, warp = tid >> 5;
    int wm = warp % 4, wn = warp / 4;
    int quad = lane >> 3, l8 = lane & 7;

    float bv2[NREP][2], bv3[NREP][2];
    #pragma unroll
    for (int p = 0; p < NREP; p++) {
        int coln = wn * 64 + p * 8 + (lane & 3) * 2;
        bv2[p][0] = b2[coln]; bv2[p][1] = b2[coln + 1];
        bv3[p][0] = b3[coln]; bv3[p][1] = b3[coln + 1];
    }

    for (int mBase = blockIdx.x * MT; mBase < M; mBase += gridDim.x * MT) {
        __syncthreads();
        for (int j = tid; j < MT * 16; j += 256) {
            int r = j >> 4, c = j & 15;
            int gr = mBase + r;
            uint4 v = (gr < M) ? ((const uint4*)in)[(size_t)gr * 16 + c]
                               : make_uint4(0u, 0u, 0u, 0u);
            *(uint4*)&As[r * LDA + c * 8] = v;
        }
        __syncthreads();

        float acc[NREP][4];
        #pragma unroll
        for (int p = 0; p < NREP; p++)
            #pragma unroll
            for (int q = 0; q < 4; q++) acc[p][q] = 0.f;

        #pragma unroll
        for (int kk = 0; kk < 128; kk += 16) {
            unsigned a[4];
            {
                int row = wm * 16 + (quad & 1) * 8 + l8;
                ldsm4(a[0], a[1], a[2], a[3],
                      sptr(&As[row * LDA + kk + (quad >> 1) * 8]));
            }
            unsigned b[NREP][2];
            #pragma unroll
            for (int p = 0; p < NREP; p += 2) {
                int n = wn * 64 + p * 8 + (quad >> 1) * 8 + l8;
                unsigned r0, r1, r2, r3;
                ldsm4(r0, r1, r2, r3, sptr(&B2s[n * LDA + kk + (quad & 1) * 8]));
                b[p][0] = r0; b[p][1] = r1;
                b[p + 1][0] = r2; b[p + 1][1] = r3;
            }
            #pragma unroll
            for (int p = 0; p < NREP; p++)
                mma16816(acc[p], a, b[p]);
        }

        __syncthreads();
        {
            int r0 = wm * 16 + (lane >> 2);
            #pragma unroll
            for (int p = 0; p < NREP; p++) {
                int coln = wn * 64 + p * 8 + (lane & 3) * 2;
                float2 v0 = make_float2(acc[p][0] + bv2[p][0], acc[p][1] + bv2[p][1]);
                float2 v1 = make_float2(acc[p][2] + bv2[p][0], acc[p][3] + bv2[p][1]);
                v0.x = sspf(v0.x); v0.y = sspf(v0.y);
                v1.x = sspf(v1.x); v1.y = sspf(v1.y);
                *(__half2*)&As[r0 * LDA + coln] = __floats2half2_rn(v0.x, v0.y);
                *(__half2*)&As[(r0 + 8) * LDA + coln] = __floats2half2_rn(v1.x, v1.y);
            }
        }
        __syncthreads();

        #pragma unroll
        for (int p = 0; p < NREP; p++)
            #pragma unroll
            for (int q = 0; q < 4; q++) acc[p][q] = 0.f;

        #pragma unroll
        for (int kk = 0; kk < 128; kk += 16) {
            unsigned a[4];
            {
                int row = wm * 16 + (quad & 1) * 8 + l8;
                ldsm4(a[0], a[1], a[2], a[3],
                      sptr(&As[row * LDA + kk + (quad >> 1) * 8]));
            }
            unsigned b[NREP][2];
            #pragma unroll
            for (int p = 0; p < NREP; p += 2) {
                int n = wn * 64 + p * 8 + (quad >> 1) * 8 + l8;
                unsigned r0, r1, r2, r3;
                ldsm4(r0, r1, r2, r3, sptr(&B3s[n * LDA + kk + (quad & 1) * 8]));
                b[p][0] = r0; b[p][1] = r1;
                b[p + 1][0] = r2; b[p + 1][1] = r3;
            }
            #pragma unroll
            for (int p = 0; p < NREP; p++)
                mma16816(acc[p], a, b[p]);
        }

        {
            int row0 = mBase + wm * 16 + (lane >> 2);
            #pragma unroll
            for (int p = 0; p < NREP; p++) {
                int coln = wn * 64 + p * 8 + (lane & 3) * 2;
                if (row0 < M) {
                    float2* dst = (float2*)(h + (size_t)row0 * Hh + coln);
                    float2 o = *dst;
                    o.x += acc[p][0] + bv3[p][0];
                    o.y += acc[p][1] + bv3[p][1];
                    *dst = o;
                }
                if (row0 + 8 < M) {
                    float2* dst = (float2*)(h + (size_t)(row0 + 8) * Hh + coln);
                    float2 o = *dst;
                    o.x += acc[p][2] + bv3[p][0];
                    o.y += acc[p][3] + bv3[p][1];
                    *dst = o;
                }
            }
        }
    }
}

// ---------------- readout GEMM with fused energy reduction -------------------
__global__ void k_mmaE(const float* __restrict__ in, const __half* __restrict__ Wt,
                       const float* __restrict__ bias, const float* __restrict__ ow2,
                       const float* __restrict__ ob2, const int* __restrict__ batch,
                       float* __restrict__ out, int M) {
    constexpr int NREP = 8, LDA = 136, MT = 128, NOUT = 64;
    extern __shared__ __half smh[];
    __half* As = smh;
    __half* Bs = smh + MT * LDA;

    int tid = threadIdx.x;
    for (int j = tid; j < NOUT * 16; j += 256) {
        int n = j >> 4, c = j & 15;
        *(uint4*)&Bs[n * LDA + c * 8] = ((const uint4*)Wt)[j];
    }
    int lane = tid & 31, warp = tid >> 5;
    int quad = lane >> 3, l8 = lane & 7;

    float bv[NREP][2], wv[NREP][2];
    #pragma unroll
    for (int p = 0; p < NREP; p++) {
        int coln = p * 8 + (lane & 3) * 2;
        bv[p][0] = bias[coln]; bv[p][1] = bias[coln + 1];
        wv[p][0] = ow2[coln];  wv[p][1] = ow2[coln + 1];
    }
    float ob = ob2[0];

    for (int mBase = blockIdx.x * MT; mBase < M; mBase += gridDim.x * MT) {
        __syncthreads();
        for (int j = tid; j < MT * 32; j += 256) {
            int r = j >> 5, c4 = j & 31;
            int gr = mBase + r;
            float4 v = (gr < M) ? ((const float4*)in)[(size_t)gr * 32 + c4]
                                : make_float4(0.f, 0.f, 0.f, 0.f);
            __half2 h0 = __floats2half2_rn(v.x, v.y);
            __half2 h1 = __floats2half2_rn(v.z, v.w);
            uint2 pk;
            pk.x = *(unsigned*)&h0;
            pk.y = *(unsigned*)&h1;
            *(uint2*)&As[r * LDA + c4 * 4] = pk;
        }
        __syncthreads();

        float acc[NREP][4];
        #pragma unroll
        for (int p = 0; p < NREP; p++)
            #pragma unroll
            for (int q = 0; q < 4; q++) acc[p][q] = 0.f;

        #pragma unroll
        for (int kk = 0; kk < 128; kk += 16) {
            unsigned a[4];
            {
                int row = warp * 16 + (quad & 1) * 8 + l8;
                ldsm4(a[0], a[1], a[2], a[3], sptr(&As[row * LDA + kk + (quad >> 1) * 8]));
            }
            unsigned b[NREP][2];
            #pragma unroll
            for (int p = 0; p < NREP; p += 2) {
                int n = p * 8 + (quad >> 1) * 8 + l8;
                unsigned r0, r1, r2, r3;
                ldsm4(r0, r1, r2, r3, sptr(&Bs[n * LDA + kk + (quad & 1) * 8]));
                b[p][0] = r0; b[p][1] = r1;
                b[p + 1][0] = r2; b[p + 1][1] = r3;
            }
            #pragma unroll
            for (int p = 0; p < NREP; p++)
                mma16816(acc[p], a, b[p]);
        }

        float e0 = 0.f, e1 = 0.f;
        #pragma unroll
        for (int p = 0; p < NREP; p++) {
            float2 v0 = make_float2(sspf(acc[p][0] + bv[p][0]), sspf(acc[p][1] + bv[p][1]));
            float2 v1 = make_float2(sspf(acc[p][2] + bv[p][0]), sspf(acc[p][3] + bv[p][1]));
            e0 = fmaf(v0.x, wv[p][0], fmaf(v0.y, wv[p][1], e0));
            e1 = fmaf(v1.x, wv[p][0], fmaf(v1.y, wv[p][1], e1));
        }
        e0 += __shfl_xor_sync(0xffffffffu, e0, 1);
        e0 += __shfl_xor_sync(0xffffffffu, e0, 2);
        e1 += __shfl_xor_sync(0xffffffffu, e1, 1);
        e1 += __shfl_xor_sync(0xffffffffu, e1, 2);
        if ((lane & 3) == 0) {
            int row0 = mBase + warp * 16 + (lane >> 2);
            if (row0 < M)     atomicAdd(&out[batch[row0]],     e0 + ob);
            if (row0 + 8 < M) atomicAdd(&out[batch[row0 + 8]], e1 + ob);
        }
    }
}

// ---------------- aggregation: one warp per node, unroll-4, fp16 out --------
__global__ void k_agg(int it) {
    const uint2* __restrict__ tab = (const uint2*)(g_tabh + (size_t)it * TT2 * Hh);
    const uint2* __restrict__ X   = (const uint2*)g_xh;
    int w = (blockIdx.x * blockDim.x + threadIdx.x) >> 5;
    if (w >= Nn) return;
    int lane = threadIdx.x & 31;
    int s   = g_off[w];
    int end = g_off[w + 1];
    ull a0 = 0ull, a1 = 0ull, b0 = 0ull, b1 = 0ull;
    ull c0 = 0ull, c1 = 0ull, d0 = 0ull, d1 = 0ull;
    for (; s + 4 <= end; s += 4) {
        ull m0 = __ldg(&g_meta[s]),     m1 = __ldg(&g_meta[s + 1]);
        ull m2 = __ldg(&g_meta[s + 2]), m3 = __ldg(&g_meta[s + 3]);
        uint2 t0 = tab[(size_t)(m0 >> 32) * 32 + lane];
        uint2 x0 = X  [(size_t)(unsigned)m0 * 32 + lane];
        uint2 t1 = tab[(size_t)(m1 >> 32) * 32 + lane];
        uint2 x1 = X  [(size_t)(unsigned)m1 * 32 + lane];
        uint2 t2 = tab[(size_t)(m2 >> 32) * 32 + lane];
        uint2 x2 = X  [(size_t)(unsigned)m2 * 32 + lane];
        uint2 t3 = tab[(size_t)(m3 >> 32) * 32 + lane];
        uint2 x3 = X  [(size_t)(unsigned)m3 * 32 + lane];
        a0 = f2fma(f2pack(__half22float2(*(__half2*)&x0.x)), f2pack(__half22float2(*(__half2*)&t0.x)), a0);
        a1 = f2fma(f2pack(__half22float2(*(__half2*)&x0.y)), f2pack(__half22float2(*(__half2*)&t0.y)), a1);
        b0 = f2fma(f2pack(__half22float2(*(__half2*)&x1.x)), f2pack(__half22float2(*(__half2*)&t1.x)), b0);
        b1 = f2fma(f2pack(__half22float2(*(__half2*)&x1.y)), f2pack(__half22float2(*(__half2*)&t1.y)), b1);
        c0 = f2fma(f2pack(__half22float2(*(__half2*)&x2.x)), f2pack(__half22float2(*(__half2*)&t2.x)), c0);
        c1 = f2fma(f2pack(__half22float2(*(__half2*)&x2.y)), f2pack(__half22float2(*(__half2*)&t2.y)), c1);
        d0 = f2fma(f2pack(__half22float2(*(__half2*)&x3.x)), f2pack(__half22float2(*(__half2*)&t3.x)), d0);
        d1 = f2fma(f2pack(__half22float2(*(__half2*)&x3.y)), f2pack(__half22float2(*(__half2*)&t3.y)), d1);
    }
    for (; s < end; s++) {
        ull m0 = __ldg(&g_meta[s]);
        uint2 t0 = tab[(size_t)(m0 >> 32) * 32 + lane];
        uint2 x0 = X  [(size_t)(unsigned)m0 * 32 + lane];
        a0 = f2fma(f2pack(__half22float2(*(__half2*)&x0.x)), f2pack(__half22float2(*(__half2*)&t0.x)), a0);
        a1 = f2fma(f2pack(__half22float2(*(__half2*)&x0.y)), f2pack(__half22float2(*(__half2*)&t0.y)), a1);
    }
    a0 = f2add(f2add(a0, b0), f2add(c0, d0));
    a1 = f2add(f2add(a1, b1), f2add(c1, d1));
    float2 p0 = f2unpack(a0);
    float2 p1 = f2unpack(a1);
    __half2 h0 = __floats2half2_rn(p0.x, p0.y);
    __half2 h1 = __floats2half2_rn(p1.x, p1.y);
    uint2 pk;
    pk.x = *(unsigned*)&h0;
    pk.y = *(unsigned*)&h1;
    ((uint2*)g_aggh)[(size_t)w * 32 + lane] = pk;
}

// ---------------------------------------------------------------------------
extern "C" void kernel_launch(void* const* d_in, const int* in_sizes, int n_in,
                              void* d_out, int out_size) {
    const float* pos   = (const float*)d_in[0];
    const float* emb   = (const float*)d_in[1];
    const float* w1    = (const float*)d_in[2];
    const float* b1    = (const float*)d_in[3];
    const float* w2    = (const float*)d_in[4];
    const float* b2    = (const float*)d_in[5];
    const float* lin1w = (const float*)d_in[6];
    const float* lin2w = (const float*)d_in[7];
    const float* lin2b = (const float*)d_in[8];
    const float* linw  = (const float*)d_in[9];
    const float* linb  = (const float*)d_in[10];
    const float* ow1   = (const float*)d_in[11];
    const float* ob1   = (const float*)d_in[12];
    const float* ow2   = (const float*)d_in[13];
    const float* ob2   = (const float*)d_in[14];
    const int*   z     = (const int*)d_in[15];
    const int*   batch = (const int*)d_in[16];
    const int*   row   = (const int*)d_in[17];
    const int*   col   = row + Ee;
    float* out = (float*)d_out;

    const size_t smem_pre1 = (size_t)(8 * 8 * 128 + 8 * 8 * NG + 256) * 4;
    const size_t smem_lin1 = (size_t)(64 + 128) * 136 * 2;
    const size_t smem_mmaE = (size_t)(128 + 64) * 136 * 2;
    const size_t smem_mma2 = (size_t)(64 + 256) * 136 * 2;
    cudaFuncSetAttribute(k_pre1, cudaFuncAttributeMaxDynamicSharedMemorySize, (int)smem_pre1);
    cudaFuncSetAttribute(k_mma<128, 64, false, false, false, true >, cudaFuncAttributeMaxDynamicSharedMemorySize, (int)smem_lin1);
    cudaFuncSetAttribute(k_mmaE, cudaFuncAttributeMaxDynamicSharedMemorySize, (int)smem_mmaE);
    cudaFuncSetAttribute(k_mma2, cudaFuncAttributeMaxDynamicSharedMemorySize, (int)smem_mma2);

    float *ph;
    __half *pxh, *paggh, *pw1t, *pw2t, *pw3t, *powt;
    cudaGetSymbolAddress((void**)&ph,    g_h);
    cudaGetSymbolAddress((void**)&pxh,   g_xh);
    cudaGetSymbolAddress((void**)&paggh, g_aggh);
    cudaGetSymbolAddress((void**)&pw1t,  g_w1t);
    cudaGetSymbolAddress((void**)&pw2t,  g_w2t);
    cudaGetSymbolAddress((void**)&pw3t,  g_w3t);
    cudaGetSymbolAddress((void**)&powt,  g_owt);
    int *pdeg;
    cudaGetSymbolAddress((void**)&pdeg, g_deg);

    cudaMemsetAsync(out, 0, Gg * sizeof(float), 0);
    cudaMemsetAsync(pdeg, 0, Nn * sizeof(int), 0);

    const int EMBWT_N = Nn * 32 + 3 * NI * Hh * Hh + 64 * Hh;
    const int PRE1_B  = PRE1_TABLE + PRE1_DEG + (EMBWT_N + 255) / 256;
    const int PRE2_B  = PRE2_SCAT + (int)(((long long)NI * TT2 * 32 + 255) / 256);

    k_pre1<<<PRE1_B, 256, smem_pre1>>>(w1, b1, w2, b2, row, emb, z, lin1w, lin2w, linw, ow1);
    k_part <<<NBLK, 256>>>();
    k_fill2<<<NBLK, 256>>>();
    k_pre2<<<PRE2_B, 256>>>(pos, row, col);

    for (int i = 0; i < NI; i++) {
        k_mma<128, 64, false, false, false, true ><<<592, 256, smem_lin1>>>(ph, pw1t + (size_t)i * Hh * Hh, nullptr, pxh, Nn);
        k_agg<<<(Nn * 32 + 255) / 256, 256>>>(i);
        k_mma2<<<592, 256, smem_mma2>>>(paggh, pw2t + (size_t)i * Hh * Hh, lin2b + i * 128,
                                        pw3t + (size_t)i * Hh * Hh, linb + i * 128, ph, Nn);
    }

    k_mmaE<<<391, 256, smem_mmaE>>>(ph, powt, ob1, ow2, ob2, batch, out, Nn);
}